// round 3
// baseline (speedup 1.0000x reference)
#include <cuda_runtime.h>
#include <cstdint>

#define HD    256      // hidden size H
#define BB    32       // batch rows per block
#define TT    256      // total timesteps
#define CONDN 192      // condition length
#define PREDN 64       // prediction length
#define PAD   34       // padded h row length (8B-aligned, de-conflicted stores)

typedef unsigned long long u64;

__device__ __forceinline__ u64 pack2(float lo, float hi) {
    u64 r; asm("mov.b64 %0,{%1,%2};" : "=l"(r) : "f"(lo), "f"(hi)); return r;
}
__device__ __forceinline__ void unpack2(u64 v, float& lo, float& hi) {
    asm("mov.b64 {%0,%1},%2;" : "=f"(lo), "=f"(hi) : "l"(v));
}
// Packed dual-fp32 FMA (Blackwell f32x2 pipe, 2 MACs per op)
__device__ __forceinline__ u64 ffma2(u64 a, u64 b, u64 c) {
    u64 d; asm("fma.rn.f32x2 %0,%1,%2,%3;" : "=l"(d) : "l"(a), "l"(b), "l"(c)); return d;
}
__device__ __forceinline__ float sigf(float x) {
    return __fdividef(1.0f, 1.0f + __expf(-x));
}
__device__ __forceinline__ float tanh_acc(float x) {
    // tanh(x) = 2*sigmoid(2x) - 1  (MUFU EX2+RCP, ~1e-6 rel err)
    return fmaf(2.0f, sigf(2.0f * x), -1.0f);
}

__global__ __launch_bounds__(256, 1) void lstm_persistent_kernel(
    const float* __restrict__ cd,     // [B, 192]
    const float* __restrict__ pred,   // [B, 64]
    const float* __restrict__ w_ih,   // [1024, 1]
    const float* __restrict__ w_hh,   // [1024, 256]
    const float* __restrict__ b_ih,   // [1024]
    const float* __restrict__ b_hh,   // [1024]
    const float* __restrict__ w_out,  // [1, 256]
    const float* __restrict__ b_out,  // [1]
    float* __restrict__ out)          // [B, 1]
{
    __shared__ float h_sh[HD][PAD];   // h_sh[k][b]: hidden unit k, batch row b
    __shared__ float x_sh[BB];

    const int tid = threadIdx.x;      // thread tid owns hidden unit j = tid
    const int j = tid;
    const int bbase = blockIdx.x * BB;

    // Per-thread stationary params: 4 gate rows {j, H+j, 2H+j, 3H+j}
    float wih[4], bias[4];
    const float4* wrow[4];
    #pragma unroll
    for (int g = 0; g < 4; g++) {
        int r = g * HD + j;
        wih[g]  = w_ih[r];
        bias[g] = b_ih[r] + b_hh[r];
        wrow[g] = (const float4*)(w_hh + (size_t)r * HD);
    }

    // zero h state
    #pragma unroll
    for (int b = 0; b < PAD; b++) h_sh[j][b] = 0.0f;

    // c state: 16 packed pairs per thread (32 batch rows)
    u64 c2[BB / 2];
    #pragma unroll
    for (int p = 0; p < BB / 2; p++) c2[p] = 0ULL;

    __syncthreads();

    for (int t = 0; t < TT; t++) {
        // stage this step's scalar inputs for the 32 batch rows
        if (tid < BB) {
            int b = bbase + tid;
            x_sh[tid] = (t < CONDN) ? cd[(size_t)b * CONDN + t]
                                    : pred[(size_t)b * PREDN + (t - CONDN)];
        }
        __syncthreads();  // x ready; previous step's h_sh writes visible

        // init gate accumulators: x*w_ih + (b_ih + b_hh), packed per batch pair
        u64 acc[4][BB / 2];
        #pragma unroll
        for (int p = 0; p < BB / 2; p++) {
            float x0 = x_sh[2 * p], x1 = x_sh[2 * p + 1];
            #pragma unroll
            for (int g = 0; g < 4; g++)
                acc[g][p] = pack2(fmaf(x0, wih[g], bias[g]),
                                  fmaf(x1, wih[g], bias[g]));
        }

        // K-reduction: gates += h @ W_hh^T   (fma.rn.f32x2, weight prefetch)
        float4 nw0 = wrow[0][0], nw1 = wrow[1][0], nw2 = wrow[2][0], nw3 = wrow[3][0];
        #pragma unroll 1
        for (int k4 = 0; k4 < HD / 4; k4++) {
            float4 w0 = nw0, w1 = nw1, w2 = nw2, w3 = nw3;
            if (k4 + 1 < HD / 4) {
                nw0 = wrow[0][k4 + 1]; nw1 = wrow[1][k4 + 1];
                nw2 = wrow[2][k4 + 1]; nw3 = wrow[3][k4 + 1];
            }
            #pragma unroll
            for (int u = 0; u < 4; u++) {
                int k = 4 * k4 + u;
                float a0 = ((const float*)&w0)[u];
                float a1 = ((const float*)&w1)[u];
                float a2 = ((const float*)&w2)[u];
                float a3 = ((const float*)&w3)[u];
                u64 wi2 = pack2(a0, a0), wf2 = pack2(a1, a1);
                u64 wg2 = pack2(a2, a2), wo2 = pack2(a3, a3);
                const u64* hrow = (const u64*)&h_sh[k][0];  // 64-bit broadcast loads
                #pragma unroll
                for (int p = 0; p < BB / 2; p++) {
                    u64 h2 = hrow[p];
                    acc[0][p] = ffma2(wi2, h2, acc[0][p]);
                    acc[1][p] = ffma2(wf2, h2, acc[1][p]);
                    acc[2][p] = ffma2(wg2, h2, acc[2][p]);
                    acc[3][p] = ffma2(wo2, h2, acc[3][p]);
                }
            }
        }

        __syncthreads();  // all reads of h_sh done before overwrite

        // activations + state update; write new h
        #pragma unroll
        for (int p = 0; p < BB / 2; p++) {
            float i0, i1, f0, f1, g0, g1, o0, o1, cl, ch;
            unpack2(acc[0][p], i0, i1);
            unpack2(acc[1][p], f0, f1);
            unpack2(acc[2][p], g0, g1);
            unpack2(acc[3][p], o0, o1);
            unpack2(c2[p], cl, ch);
            cl = sigf(f0) * cl + sigf(i0) * tanh_acc(g0);
            ch = sigf(f1) * ch + sigf(i1) * tanh_acc(g1);
            c2[p] = pack2(cl, ch);
            h_sh[j][2 * p]     = sigf(o0) * tanh_acc(cl);
            h_sh[j][2 * p + 1] = sigf(o1) * tanh_acc(ch);
        }
        // next iteration's top __syncthreads publishes h_sh
    }
    __syncthreads();

    // epilogue: out[b] = sigmoid(h_last[b] . w_out + b_out)
    const int warp = tid >> 5, lane = tid & 31;
    const float bo = b_out[0];
    #pragma unroll
    for (int q = 0; q < 4; q++) {
        int b = warp * 4 + q;
        float s = 0.0f;
        #pragma unroll
        for (int m = 0; m < 8; m++) {
            int jj = lane + 32 * m;
            s += h_sh[jj][b] * w_out[jj];
        }
        #pragma unroll
        for (int off = 16; off > 0; off >>= 1)
            s += __shfl_xor_sync(0xffffffffu, s, off);
        if (lane == 0) out[bbase + b] = sigf(s + bo);
    }
}

extern "C" void kernel_launch(void* const* d_in, const int* in_sizes, int n_in,
                              void* d_out, int out_size) {
    const float* cd    = (const float*)d_in[0];
    const float* pred  = (const float*)d_in[1];
    const float* w_ih  = (const float*)d_in[2];
    const float* w_hh  = (const float*)d_in[3];
    const float* b_ih  = (const float*)d_in[4];
    const float* b_hh  = (const float*)d_in[5];
    const float* w_out = (const float*)d_in[6];
    const float* b_out = (const float*)d_in[7];
    (void)in_sizes; (void)n_in; (void)out_size;

    lstm_persistent_kernel<<<4096 / BB, 256>>>(
        cd, pred, w_ih, w_hh, b_ih, b_hh, w_out, b_out, (float*)d_out);
}

// round 5
// speedup vs baseline: 4.7955x; 4.7955x over previous
#include <cuda_runtime.h>
#include <cuda_fp16.h>
#include <cstdint>

// ---------------- problem constants ----------------
#define HD      256
#define TT      256
#define CONDN   192
#define PREDN   64
#define KP      272          // padded K' = 256 h + x + 1 + 14 zero
#define KT      17           // k16 steps
#define ASTR    272          // A row stride bytes (128 fp16 + 8 pad) -> conflict-free ldmatrix
#define BSTR    560          // B row stride bytes (272 fp16 + 8 pad) -> conflict-free ldmatrix
#define SB_A    0            // A: 272 rows x 272B = 73984
#define SB_B    73984        // B: 256 rows x 560B = 143360
#define SMEMSZ  (SB_B + 256 * BSTR)   // 217344
#define THREADS 512
#define CLUSTER 4

// ---------------- device scratch: prepped weights ----------------
__device__ __align__(16) __half Wp_g[1024 * KP];

// ---------------- helpers ----------------
__device__ __forceinline__ uint32_t smem_u32(const void* p) {
    uint32_t a;
    asm("{ .reg .u64 t; cvta.to.shared.u64 t, %1; cvt.u32.u64 %0, t; }" : "=r"(a) : "l"(p));
    return a;
}
__device__ __forceinline__ float sigp(float x) {          // precise sigmoid (EX2+RCP)
    return __fdividef(1.0f, 1.0f + __expf(-x));
}
__device__ __forceinline__ float tanhp(float x) {         // precise tanh
    return __fdividef(2.0f, 1.0f + __expf(-2.0f * x)) - 1.0f;
}

// ---------------- prep: permute + K-extend + fp16 ----------------
__global__ void prep_weights(const float* __restrict__ w_hh, const float* __restrict__ w_ih,
                             const float* __restrict__ b_ih, const float* __restrict__ b_hh) {
    int n = blockIdx.x;                  // 0..1023, n = 4j+g (gate-interleaved)
    int j = n >> 2, g = n & 3;
    int src = g * HD + j;                // PyTorch gate order i,f,g,o
    __half* dst = Wp_g + (size_t)n * KP;
    for (int k = threadIdx.x; k < KP; k += blockDim.x) {
        float v = 0.0f;
        if (k < HD)          v = w_hh[(size_t)src * HD + k];
        else if (k == HD)    v = w_ih[src];
        else if (k == HD + 1) v = b_ih[src] + b_hh[src];
        dst[k] = __float2half(v);
    }
}

// ---------------- main: cluster-of-4 persistent LSTM ----------------
__global__ __launch_bounds__(THREADS, 1) void lstm_mma_kernel(
    const float* __restrict__ cd,     // [B,192]
    const float* __restrict__ pred,   // [B,64]
    const float* __restrict__ w_out,  // [1,256]
    const float* __restrict__ b_out,  // [1]
    float* __restrict__ out)          // [B,1]
{
    extern __shared__ char smem[];
    const uint32_t sb = smem_u32(smem);
    const int tid = threadIdx.x, lane = tid & 31, wid = tid >> 5;
    const int warpM = wid & 3;        // 4 warps over M: 32 rows each
    const int warpN = wid >> 2;       // 4 warps over N: 64 cols each
    uint32_t rank;
    asm("mov.u32 %0, %%cluster_ctarank;" : "=r"(rank));
    const int bbase = (blockIdx.x >> 2) * 128;   // batch rows of this cluster

    // mapa'd A-base address in every cluster CTA (stable across steps)
    uint32_t abase[CLUSTER];
    #pragma unroll
    for (int r = 0; r < CLUSTER; r++)
        asm("mapa.shared::cluster.u32 %0, %1, %2;" : "=r"(abase[r]) : "r"(sb + SB_A), "r"(r));

    // ---- load this CTA's N-quarter of Wp into SMEM (once, stationary) ----
    {
        const uint4* src = (const uint4*)(Wp_g + (size_t)rank * 256 * KP);
        for (int i = tid; i < 256 * 34; i += THREADS) {
            int row = i / 34, g16 = i % 34;
            *(uint4*)(smem + SB_B + row * BSTR + g16 * 16) = src[(size_t)row * 34 + g16];
        }
    }
    // ---- zero A (h_0 = 0, zero pad rows) ----
    for (int i = tid; i < (272 * ASTR) / 4; i += THREADS)
        ((uint32_t*)(smem + SB_A))[i] = 0u;
    __syncthreads();
    if (tid < 128) {  // ones row (k=257) and x_0 (k=256)
        *(__half*)(smem + SB_A + 257 * ASTR + tid * 2) = __float2half(1.0f);
        *(__half*)(smem + SB_A + 256 * ASTR + tid * 2) =
            __float2half(cd[(size_t)(bbase + tid) * CONDN]);
    }
    __syncthreads();

    // ---- precomputed lane addressing ----
    // A ldmatrix.x4.trans: quad q: k_off=(q&... lanes: k_row = (l&7)+((l>>4)<<3), m_chunk += ((l>>3)&1)<<3
    const int aRowSel = (lane & 7) + ((lane >> 4) << 3);
    const int aMSel   = ((lane >> 3) & 1) << 3;
    uint32_t aAddr0[2];
    #pragma unroll
    for (int mt = 0; mt < 2; mt++)
        aAddr0[mt] = sb + SB_A + (uint32_t)aRowSel * ASTR
                   + (uint32_t)(warpM * 32 + mt * 16 + aMSel) * 2;
    // B ldmatrix.x4 (non-trans): n_row = (l&7)+((l>>3)&1)*8, k halves by (l>>4)
    const int bRowSel = (lane & 7) + (((lane >> 3) & 1) << 3);
    const int bKSel   = ((lane >> 4) & 1) << 3;
    uint32_t bAddr0[4];
    #pragma unroll
    for (int nt2 = 0; nt2 < 4; nt2++)
        bAddr0[nt2] = sb + SB_B + (uint32_t)(warpN * 64 + nt2 * 16 + bRowSel) * BSTR
                    + (uint32_t)bKSel * 2;

    // epilogue lane mapping (from m16n8 D fragment layout)
    const bool evenlane = ((lane & 1) == 0);
    const int rbase0 = warpM * 32 + (lane >> 2) + (evenlane ? 0 : 8);
    const int joff   = warpN * 16 + ((lane >> 1) & 1);   // + nt*2 per tile

    float cst[16];                     // c state, fixed (row,unit) per lane per tile
    #pragma unroll
    for (int i = 0; i < 16; i++) cst[i] = 0.0f;

    for (int t = 0; t < TT; t++) {
        float d[2][8][4];
        #pragma unroll
        for (int mt = 0; mt < 2; mt++)
            #pragma unroll
            for (int nt = 0; nt < 8; nt++)
                #pragma unroll
                for (int e = 0; e < 4; e++) d[mt][nt][e] = 0.0f;

        // ---- GEMM: D[128,256] += A[128,K']*B^T ----
        #pragma unroll 1
        for (int kt = 0; kt < KT; kt++) {
            uint32_t a[2][4];
            #pragma unroll
            for (int mt = 0; mt < 2; mt++) {
                uint32_t ad = aAddr0[mt] + (uint32_t)kt * (16 * ASTR);
                asm volatile("ldmatrix.sync.aligned.m8n8.x4.trans.shared.b16 {%0,%1,%2,%3}, [%4];"
                    : "=r"(a[mt][0]), "=r"(a[mt][1]), "=r"(a[mt][2]), "=r"(a[mt][3]) : "r"(ad));
            }
            #pragma unroll
            for (int nt2 = 0; nt2 < 4; nt2++) {
                uint32_t b0, b1, b2, b3;
                uint32_t bd = bAddr0[nt2] + (uint32_t)kt * 32;
                asm volatile("ldmatrix.sync.aligned.m8n8.x4.shared.b16 {%0,%1,%2,%3}, [%4];"
                    : "=r"(b0), "=r"(b1), "=r"(b2), "=r"(b3) : "r"(bd));
                #pragma unroll
                for (int mt = 0; mt < 2; mt++) {
                    asm volatile("mma.sync.aligned.m16n8k16.row.col.f32.f16.f16.f32 "
                        "{%0,%1,%2,%3},{%4,%5,%6,%7},{%8,%9},{%0,%1,%2,%3};"
                        : "+f"(d[mt][2*nt2][0]), "+f"(d[mt][2*nt2][1]),
                          "+f"(d[mt][2*nt2][2]), "+f"(d[mt][2*nt2][3])
                        : "r"(a[mt][0]), "r"(a[mt][1]), "r"(a[mt][2]), "r"(a[mt][3]),
                          "r"(b0), "r"(b2));
                    asm volatile("mma.sync.aligned.m16n8k16.row.col.f32.f16.f16.f32 "
                        "{%0,%1,%2,%3},{%4,%5,%6,%7},{%8,%9},{%0,%1,%2,%3};"
                        : "+f"(d[mt][2*nt2+1][0]), "+f"(d[mt][2*nt2+1][1]),
                          "+f"(d[mt][2*nt2+1][2]), "+f"(d[mt][2*nt2+1][3])
                        : "r"(a[mt][0]), "r"(a[mt][1]), "r"(a[mt][2]), "r"(a[mt][3]),
                          "r"(b1), "r"(b3));
                }
            }
        }
        __syncthreads();   // all warps done reading A before h/x overwrite

        // ---- epilogue: gates -> c,h ; h broadcast to all cluster CTAs ----
        #pragma unroll
        for (int mt = 0; mt < 2; mt++) {
            #pragma unroll
            for (int nt = 0; nt < 8; nt++) {
                float d0 = d[mt][nt][0], d1 = d[mt][nt][1];
                float d2 = d[mt][nt][2], d3 = d[mt][nt][3];
                // pair exchange: even lane owns (i,f) rows r,r+8; odd owns (g,o)
                float s0 = evenlane ? d2 : d0;
                float s1 = evenlane ? d3 : d1;
                float e0 = __shfl_xor_sync(0xffffffffu, s0, 1);
                float e1 = __shfl_xor_sync(0xffffffffu, s1, 1);
                float gi = evenlane ? d0 : e0;
                float gf = evenlane ? d1 : e1;
                float gg = evenlane ? e0 : d2;
                float go = evenlane ? e1 : d3;
                float cc = cst[mt * 8 + nt];
                cc = sigp(gf) * cc + sigp(gi) * tanhp(gg);
                cst[mt * 8 + nt] = cc;
                float h = sigp(go) * tanhp(cc);
                unsigned short hb = __half_as_ushort(__float2half(h));
                int j_cta = joff + nt * 2;                     // unit within this CTA
                uint32_t off = (uint32_t)(rank * 64 + j_cta) * ASTR
                             + (uint32_t)(rbase0 + mt * 16) * 2;
                #pragma unroll
                for (int r = 0; r < CLUSTER; r++)
                    asm volatile("st.shared::cluster.b16 [%0], %1;"
                                 :: "r"(abase[r] + off), "h"(hb) : "memory");
            }
        }
        // stage x_{t+1} locally (row 256)
        if (tid < 128 && t < TT - 1) {
            int tn = t + 1, b = bbase + tid;
            float x = (tn < CONDN) ? cd[(size_t)b * CONDN + tn]
                                   : pred[(size_t)b * PREDN + (tn - CONDN)];
            *(__half*)(smem + SB_A + 256 * ASTR + tid * 2) = __float2half(x);
        }
        // cluster barrier: release remote h stores / acquire before next reads
        asm volatile("barrier.cluster.arrive.aligned;" ::: "memory");
        asm volatile("barrier.cluster.wait.aligned;" ::: "memory");
    }

    // ---- output: rank 0 has full h_T in its A buffer ----
    if (rank == 0 && tid < 128) {
        float acc = b_out[0];
        #pragma unroll 8
        for (int j = 0; j < HD; j++)
            acc += __half2float(*(const __half*)(smem + SB_A + j * ASTR + tid * 2))
                 * __ldg(&w_out[j]);
        out[bbase + tid] = sigp(acc);
    }
}

extern "C" void kernel_launch(void* const* d_in, const int* in_sizes, int n_in,
                              void* d_out, int out_size) {
    const float* cd    = (const float*)d_in[0];
    const float* pred  = (const float*)d_in[1];
    const float* w_ih  = (const float*)d_in[2];
    const float* w_hh  = (const float*)d_in[3];
    const float* b_ih  = (const float*)d_in[4];
    const float* b_hh  = (const float*)d_in[5];
    const float* w_out = (const float*)d_in[6];
    const float* b_out = (const float*)d_in[7];
    (void)in_sizes; (void)n_in; (void)out_size;

    static bool once = false;
    if (!once) {
        cudaFuncSetAttribute(lstm_mma_kernel,
                             cudaFuncAttributeMaxDynamicSharedMemorySize, SMEMSZ);
        once = true;
    }

    prep_weights<<<1024, 64>>>(w_hh, w_ih, b_ih, b_hh);

    cudaLaunchConfig_t cfg = {};
    cfg.gridDim = dim3(128, 1, 1);
    cfg.blockDim = dim3(THREADS, 1, 1);
    cfg.dynamicSmemBytes = SMEMSZ;
    cfg.stream = 0;
    cudaLaunchAttribute attrs[1];
    attrs[0].id = cudaLaunchAttributeClusterDimension;
    attrs[0].val.clusterDim = {CLUSTER, 1, 1};
    cfg.attrs = attrs;
    cfg.numAttrs = 1;
    cudaLaunchKernelEx(&cfg, lstm_mma_kernel, cd, pred, w_out, b_out, (float*)d_out);
}